// round 4
// baseline (speedup 1.0000x reference)
#include <cuda_runtime.h>
#include <cstdint>

// nu_grid_sampler: out[b,c,n] = x[b,c,px,py], x:(8,128,256,256) f32,
// coords:(8,32768,2) f32, out:(8,128,32768) f32.
//
// R4: dense plane streaming through smem (R3) was right, but regs=64 @1024thr
// consumed the whole RF -> 1 block/SM -> stage-boundary bubbles capped DRAM at
// 52%. This version targets 2 blocks/SM: 2x32KB stage buffers (8 stages of
// 8192 px), <=32 regs (__launch_bounds__(1024,2)) by re-reading the packed
// indices from L2 each stage instead of caching them in registers.

#define GS_B 8
#define GS_C 128
#define GS_NX 256
#define GS_NY 256
#define GS_N 32768
#define GS_PIX (GS_NX * GS_NY)            // 65536
#define GS_HALF_N (GS_N / 2)              // 16384 pairs
#define STAGE_PIX 8192                     // pixels per smem stage (32KB)
#define NUM_STAGES (GS_PIX / STAGE_PIX)    // 8
#define K2_THREADS 1024
#define PAIRS_PER_THREAD (GS_HALF_N / K2_THREADS)  // 16

// g_pack[b*16384 + j] = idx(n=j) | (idx(n=j+16384) << 16)
__device__ unsigned int g_pack[GS_B * GS_HALF_N];   // 512 KB scratch (L2-resident)

__device__ __forceinline__ unsigned int compute_idx(float cy, float cx) {
    float pxf = fminf(fmaxf(cx * (float)(GS_NX - 1), 0.0f), (float)GS_NX);
    float pyf = fminf(fmaxf(cy * (float)(GS_NY - 1), 0.0f), (float)GS_NY);
    int idx = (int)pxf * GS_NY + (int)pyf;
    return (unsigned int)min(idx, GS_PIX - 1);       // take_along_axis clamp
}

__global__ __launch_bounds__(256)
void idx_kernel(const float* __restrict__ coords) {
    int j = blockIdx.x * blockDim.x + threadIdx.x;   // 0..16383
    int b = blockIdx.y;
    const float2* cb = reinterpret_cast<const float2*>(coords) + (size_t)b * GS_N;
    float2 c_lo = cb[j];
    float2 c_hi = cb[j + GS_HALF_N];
    g_pack[b * GS_HALF_N + j] =
        compute_idx(c_lo.x, c_lo.y) | (compute_idx(c_hi.x, c_hi.y) << 16);
}

__device__ __forceinline__ void cp_async16(void* smem_dst, const void* gmem_src) {
    unsigned int s;
    asm("{ .reg .u64 t; cvta.to.shared.u64 t, %1; cvt.u32.u64 %0, t; }"
        : "=r"(s) : "l"(smem_dst));
    asm volatile("cp.async.cg.shared.global [%0], [%1], 16;\n" :: "r"(s), "l"(gmem_src));
}

__global__ __launch_bounds__(K2_THREADS, 2)
void gather_kernel(const float* __restrict__ x, float* __restrict__ out) {
    extern __shared__ float sbuf[];                  // 2 * STAGE_PIX floats = 64KB
    const int tid = threadIdx.x;
    const int bc  = blockIdx.x;                      // b*128 + c
    const int b   = bc >> 7;

    const float* __restrict__ plane = x + ((size_t)bc << 16);
    float* __restrict__ ob          = out + ((size_t)bc << 15);
    const unsigned int* __restrict__ pk = g_pack + b * GS_HALF_N + tid;

    // Prologue: stage 0 -> buf 0 (32KB = 2 rounds of 16B/thread)
    #pragma unroll
    for (int q = 0; q < STAGE_PIX / (K2_THREADS * 4); ++q)       // 2 iters
        cp_async16(&sbuf[(q * K2_THREADS + tid) * 4],
                   &plane[(q * K2_THREADS + tid) * 4]);
    asm volatile("cp.async.commit_group;\n");

    #pragma unroll
    for (int s = 0; s < NUM_STAGES; ++s) {
        const float* cur = sbuf + (s & 1) * STAGE_PIX;
        if (s + 1 < NUM_STAGES) {
            float* nxt = sbuf + ((s + 1) & 1) * STAGE_PIX;
            const float* src = plane + (size_t)(s + 1) * STAGE_PIX;
            #pragma unroll
            for (int q = 0; q < STAGE_PIX / (K2_THREADS * 4); ++q)
                cp_async16(&nxt[(q * K2_THREADS + tid) * 4],
                           &src[(q * K2_THREADS + tid) * 4]);
            asm volatile("cp.async.commit_group;\n");
            asm volatile("cp.async.wait_group 1;\n");
        } else {
            asm volatile("cp.async.wait_group 0;\n");
        }
        __syncthreads();

        // Scan the point list (re-read from L2 each stage to stay <=32 regs);
        // gather hits from smem, coalesced-predicated stores.
        const unsigned int us = (unsigned int)s;
        #pragma unroll
        for (int k = 0; k < PAIRS_PER_THREAD; ++k) {
            unsigned int pr = __ldg(pk + (k << 10));
            unsigned int lo = pr & 0xFFFFu;
            unsigned int hi = pr >> 16;
            int j = tid + (k << 10);
            if ((lo >> 13) == us) ob[j]             = cur[lo & (STAGE_PIX - 1)];
            if ((hi >> 13) == us) ob[j + GS_HALF_N] = cur[hi & (STAGE_PIX - 1)];
        }
        __syncthreads();   // buffer s&1 is refilled at iteration s+2
    }
}

extern "C" void kernel_launch(void* const* d_in, const int* in_sizes, int n_in,
                              void* d_out, int out_size) {
    const float* x      = (const float*)d_in[0];   // (8,128,256,256) f32
    const float* coords = (const float*)d_in[1];   // (8,32768,2) f32
    float* out          = (float*)d_out;           // (8,128,32768) f32

    static int smem_set = 0;
    if (!smem_set) {
        cudaFuncSetAttribute(gather_kernel,
                             cudaFuncAttributeMaxDynamicSharedMemorySize,
                             2 * STAGE_PIX * sizeof(float));
        smem_set = 1;
    }

    idx_kernel<<<dim3(GS_HALF_N / 256, GS_B), 256>>>(coords);
    gather_kernel<<<GS_B * GS_C, K2_THREADS, 2 * STAGE_PIX * sizeof(float)>>>(x, out);
}

// round 5
// speedup vs baseline: 1.8303x; 1.8303x over previous
#include <cuda_runtime.h>
#include <cstdint>

// nu_grid_sampler: out[b,c,n] = x[b,c,px,py], x:(8,128,256,256) f32,
// coords:(8,32768,2) f32, out:(8,128,32768) f32.
//
// R5 = R3 (winning structure: dense plane streaming, 4 x 16K-pixel stages,
// indices cached in registers, coalesced-predicated stores) + TRIPLE buffering
// (3 x 64KB smem) so stage copies for s+1 and s+2 are in flight while stage s
// is gathered -> stage-boundary bubbles (R3's limiter: DRAM 52%, issue 18%,
// nothing saturated) are removed. 1 block/SM by design; smem 192KB.

#define GS_B 8
#define GS_C 128
#define GS_NX 256
#define GS_NY 256
#define GS_N 32768
#define GS_PIX (GS_NX * GS_NY)            // 65536
#define GS_HALF_N (GS_N / 2)              // 16384 pairs
#define STAGE_PIX 16384                    // pixels per stage (64KB)
#define NUM_STAGES 4
#define NUM_BUFS 3
#define K2_THREADS 1024
#define PAIRS_PER_THREAD (GS_HALF_N / K2_THREADS)  // 16

// g_pack[b*16384 + j] = idx(n=j) | (idx(n=j+16384) << 16)
__device__ unsigned int g_pack[GS_B * GS_HALF_N];   // 512 KB scratch

__device__ __forceinline__ unsigned int compute_idx(float cy, float cx) {
    float pxf = fminf(fmaxf(cx * (float)(GS_NX - 1), 0.0f), (float)GS_NX);
    float pyf = fminf(fmaxf(cy * (float)(GS_NY - 1), 0.0f), (float)GS_NY);
    int idx = (int)pxf * GS_NY + (int)pyf;
    return (unsigned int)min(idx, GS_PIX - 1);       // take_along_axis clamp
}

__global__ __launch_bounds__(256)
void idx_kernel(const float* __restrict__ coords) {
    int j = blockIdx.x * blockDim.x + threadIdx.x;   // 0..16383
    int b = blockIdx.y;
    const float2* cb = reinterpret_cast<const float2*>(coords) + (size_t)b * GS_N;
    float2 c_lo = cb[j];
    float2 c_hi = cb[j + GS_HALF_N];
    g_pack[b * GS_HALF_N + j] =
        compute_idx(c_lo.x, c_lo.y) | (compute_idx(c_hi.x, c_hi.y) << 16);
}

__device__ __forceinline__ void cp_async16(void* smem_dst, const void* gmem_src) {
    unsigned int s;
    asm("{ .reg .u64 t; cvta.to.shared.u64 t, %1; cvt.u32.u64 %0, t; }"
        : "=r"(s) : "l"(smem_dst));
    asm volatile("cp.async.cg.shared.global [%0], [%1], 16;\n" :: "r"(s), "l"(gmem_src));
}

// Copy one 16K-pixel stage (64KB): 4 rounds of 16B per thread.
__device__ __forceinline__ void copy_stage(float* dst, const float* src, int tid) {
    #pragma unroll
    for (int q = 0; q < STAGE_PIX / (K2_THREADS * 4); ++q)       // 4 iters
        cp_async16(&dst[(q * K2_THREADS + tid) * 4],
                   &src[(q * K2_THREADS + tid) * 4]);
    asm volatile("cp.async.commit_group;\n");
}

__global__ __launch_bounds__(K2_THREADS, 1)
void gather_kernel(const float* __restrict__ x, float* __restrict__ out) {
    extern __shared__ float sbuf[];                  // 3 * STAGE_PIX floats = 192KB
    const int tid = threadIdx.x;
    const int bc  = blockIdx.x;                      // b*128 + c
    const int b   = bc >> 7;

    const float* __restrict__ plane = x + ((size_t)bc << 16);
    float* __restrict__ ob          = out + ((size_t)bc << 15);

    // Cache this thread's 16 packed index pairs in registers (coalesced reads).
    unsigned int pair[PAIRS_PER_THREAD];
    const unsigned int* __restrict__ pk = g_pack + b * GS_HALF_N + tid;
    #pragma unroll
    for (int k = 0; k < PAIRS_PER_THREAD; ++k)
        pair[k] = pk[k << 10];

    // Prologue: prefetch stages 0 and 1 (pipeline depth 2 ahead).
    copy_stage(sbuf + 0 * STAGE_PIX, plane + 0 * (size_t)STAGE_PIX, tid);
    copy_stage(sbuf + 1 * STAGE_PIX, plane + 1 * (size_t)STAGE_PIX, tid);

    #pragma unroll
    for (int s = 0; s < NUM_STAGES; ++s) {
        // Issue copy for s+2 (into buffer (s+2)%3, free since gather s-1 done).
        if (s + 2 < NUM_STAGES)
            copy_stage(sbuf + ((s + 2) % NUM_BUFS) * STAGE_PIX,
                       plane + (size_t)(s + 2) * STAGE_PIX, tid);
        // Wait until copy s is complete (in-order groups).
        if (s == 0)      asm volatile("cp.async.wait_group 2;\n");
        else if (s == 1) asm volatile("cp.async.wait_group 2;\n");
        else if (s == 2) asm volatile("cp.async.wait_group 1;\n");
        else             asm volatile("cp.async.wait_group 0;\n");
        __syncthreads();

        const float* cur = sbuf + (s % NUM_BUFS) * STAGE_PIX;
        const unsigned int us = (unsigned int)s;
        #pragma unroll
        for (int k = 0; k < PAIRS_PER_THREAD; ++k) {
            unsigned int pr = pair[k];
            unsigned int lo = pr & 0xFFFFu;
            unsigned int hi = pr >> 16;
            int j = tid + (k << 10);
            if ((lo >> 14) == us) ob[j]             = cur[lo & (STAGE_PIX - 1)];
            if ((hi >> 14) == us) ob[j + GS_HALF_N] = cur[hi & (STAGE_PIX - 1)];
        }
        __syncthreads();   // buffer (s%3) must be fully read before s+1 reuses slot math
    }
}

extern "C" void kernel_launch(void* const* d_in, const int* in_sizes, int n_in,
                              void* d_out, int out_size) {
    const float* x      = (const float*)d_in[0];   // (8,128,256,256) f32
    const float* coords = (const float*)d_in[1];   // (8,32768,2) f32
    float* out          = (float*)d_out;           // (8,128,32768) f32

    static int smem_set = 0;
    if (!smem_set) {
        cudaFuncSetAttribute(gather_kernel,
                             cudaFuncAttributeMaxDynamicSharedMemorySize,
                             NUM_BUFS * STAGE_PIX * sizeof(float));
        smem_set = 1;
    }

    idx_kernel<<<dim3(GS_HALF_N / 256, GS_B), 256>>>(coords);
    gather_kernel<<<GS_B * GS_C, K2_THREADS,
                    NUM_BUFS * STAGE_PIX * sizeof(float)>>>(x, out);
}